// round 2
// baseline (speedup 1.0000x reference)
#include <cuda_runtime.h>

#define MARGIN 0.1f

// Persistent device scratch (no allocations allowed). Reset by the last block
// each call, so every graph replay sees the same initial state.
__device__ double       g_total = 0.0;
__device__ unsigned int g_count = 0u;

__global__ void __launch_bounds__(256, 8)
margin_loss_kernel(const float* __restrict__ x,
                   const int* __restrict__ labels,   // int32 (JAX x64 disabled)
                   float* __restrict__ out,
                   int N)
{
    const int warp_in_block = threadIdx.x >> 5;   // 0..7
    const int lane          = threadIdx.x & 31;
    const int row           = blockIdx.x * 8 + warp_in_block;

    float wsum = 0.0f;

    if (row < N) {
        // One warp = one row of 128 floats. lane loads 4 consecutive floats.
        const float4 v = reinterpret_cast<const float4*>(x)[(size_t)row * 32 + lane];
        const int label = labels[row];            // broadcast load, cheap

        // Pick the candidate component; (label & 3) is warp-uniform.
        const int comp = label & 3;
        float cand = (comp == 0) ? v.x : (comp == 1) ? v.y : (comp == 2) ? v.z : v.w;
        const float c = __shfl_sync(0xffffffffu, cand, label >> 2);

        const float b = MARGIN - c;
        wsum  = fmaxf(b + v.x, 0.0f);
        wsum += fmaxf(b + v.y, 0.0f);
        wsum += fmaxf(b + v.z, 0.0f);
        wsum += fmaxf(b + v.w, 0.0f);

        // Warp reduction.
        #pragma unroll
        for (int o = 16; o > 0; o >>= 1)
            wsum += __shfl_down_sync(0xffffffffu, wsum, o);

        // The j == label term contributed exactly max(0, MARGIN) = MARGIN; remove it.
        if (lane == 0) wsum -= MARGIN;
    }

    __shared__ float  warp_sums[8];
    __shared__ bool   is_last;

    if (lane == 0) warp_sums[warp_in_block] = wsum;
    __syncthreads();

    if (threadIdx.x == 0) {
        double bsum = 0.0;
        #pragma unroll
        for (int w = 0; w < 8; w++) bsum += (double)warp_sums[w];
        atomicAdd(&g_total, bsum);
        __threadfence();
        unsigned int t = atomicAdd(&g_count, 1u);
        is_last = (t == gridDim.x - 1);
    }
    __syncthreads();

    if (is_last && threadIdx.x == 0) {
        const double total = g_total;
        // mean over N * (G-1) pairs, G = 128
        out[0] = (float)(total / ((double)N * 127.0));
        // Reset for the next (graph-replayed) call.
        g_total = 0.0;
        g_count = 0u;
    }
}

extern "C" void kernel_launch(void* const* d_in, const int* in_sizes, int n_in,
                              void* d_out, int out_size)
{
    const float* x      = (const float*)d_in[0];
    const int*   labels = (const int*)d_in[1];
    float*       out    = (float*)d_out;

    const int N = in_sizes[1];                 // labels count = rows
    const int blocks = (N + 7) / 8;            // 8 rows (warps) per block

    margin_loss_kernel<<<blocks, 256>>>(x, labels, out, N);
}

// round 3
// speedup vs baseline: 2.2266x; 2.2266x over previous
#include <cuda_runtime.h>

#define MARGIN 0.1f
#define ROWS_PER_WARP 8

// Persistent device scratch (no allocations allowed). Reset by the last block
// each call, so every graph replay sees the same initial state.
__device__ double       g_total = 0.0;
__device__ unsigned int g_count = 0u;

__global__ void __launch_bounds__(256, 8)
margin_loss_kernel(const float* __restrict__ x,
                   const int* __restrict__ labels,   // int32 (JAX x64 disabled)
                   float* __restrict__ out,
                   int N)
{
    const int warp_in_block = threadIdx.x >> 5;   // 0..7
    const int lane          = threadIdx.x & 31;
    // Each warp owns ROWS_PER_WARP consecutive rows.
    const int base = (blockIdx.x * 8 + warp_in_block) * ROWS_PER_WARP;

    float wsum = 0.0f;

    if (base < N) {   // N is a multiple of 64, so the whole batch is in-bounds
        // 8 independent 16B loads issued back-to-back -> MLP ~ 8 per thread.
        const float4* x4 = reinterpret_cast<const float4*>(x);
        float4 v[ROWS_PER_WARP];
        #pragma unroll
        for (int k = 0; k < ROWS_PER_WARP; k++)
            v[k] = __ldcs(&x4[((size_t)(base + k)) * 32 + lane]);

        // Lanes 0..7 fetch the 8 labels in one coalesced transaction.
        int lab = 0;
        if (lane < ROWS_PER_WARP) lab = labels[base + lane];

        #pragma unroll
        for (int k = 0; k < ROWS_PER_WARP; k++) {
            const int label = __shfl_sync(0xffffffffu, lab, k);
            // (label & 3) is warp-uniform -> branchless-ish uniform select.
            const int comp = label & 3;
            float cand = (comp == 0) ? v[k].x : (comp == 1) ? v[k].y
                       : (comp == 2) ? v[k].z : v[k].w;
            const float c = __shfl_sync(0xffffffffu, cand, label >> 2);

            const float b = MARGIN - c;
            wsum += fmaxf(b + v[k].x, 0.0f);
            wsum += fmaxf(b + v[k].y, 0.0f);
            wsum += fmaxf(b + v[k].z, 0.0f);
            wsum += fmaxf(b + v[k].w, 0.0f);
        }

        // One warp reduction for all 8 rows.
        #pragma unroll
        for (int o = 16; o > 0; o >>= 1)
            wsum += __shfl_down_sync(0xffffffffu, wsum, o);

        // Each row's j == label term contributed exactly MARGIN; remove all 8.
        if (lane == 0) wsum -= MARGIN * (float)ROWS_PER_WARP;
    }

    __shared__ float  warp_sums[8];
    __shared__ bool   is_last;

    if (lane == 0) warp_sums[warp_in_block] = wsum;
    __syncthreads();

    if (threadIdx.x == 0) {
        double bsum = 0.0;
        #pragma unroll
        for (int w = 0; w < 8; w++) bsum += (double)warp_sums[w];
        atomicAdd(&g_total, bsum);
        __threadfence();
        unsigned int t = atomicAdd(&g_count, 1u);
        is_last = (t == gridDim.x - 1);
    }
    __syncthreads();

    if (is_last && threadIdx.x == 0) {
        const double total = g_total;
        // mean over N * (G-1) pairs, G = 128
        out[0] = (float)(total / ((double)N * 127.0));
        // Reset for the next (graph-replayed) call.
        g_total = 0.0;
        g_count = 0u;
    }
}

extern "C" void kernel_launch(void* const* d_in, const int* in_sizes, int n_in,
                              void* d_out, int out_size)
{
    const float* x      = (const float*)d_in[0];
    const int*   labels = (const int*)d_in[1];
    float*       out    = (float*)d_out;

    const int N = in_sizes[1];                      // labels count = rows
    const int rows_per_block = 8 * ROWS_PER_WARP;   // 64
    const int blocks = (N + rows_per_block - 1) / rows_per_block;

    margin_loss_kernel<<<blocks, 256>>>(x, labels, out, N);
}

// round 4
// speedup vs baseline: 2.4024x; 1.0789x over previous
#include <cuda_runtime.h>

#define MARGIN 0.1f
#define ROWS_PER_WARP 8

// Persistent device scratch (no allocations allowed). Reset by the last block
// each call, so every graph replay sees the same initial state.
__device__ double       g_total = 0.0;
__device__ unsigned int g_count = 0u;

// (256, 4): 64-reg budget so all 8 float4 loads stay in flight (MLP_p1=8),
// while 4 CTAs x 8 warps = 32 warps/SM keeps full warp occupancy.
__global__ void __launch_bounds__(256, 4)
margin_loss_kernel(const float* __restrict__ x,
                   const int* __restrict__ labels,   // int32 (JAX x64 disabled)
                   float* __restrict__ out,
                   int N)
{
    const int warp_in_block = threadIdx.x >> 5;   // 0..7
    const int lane          = threadIdx.x & 31;
    // Each warp owns ROWS_PER_WARP consecutive rows.
    const int base = (blockIdx.x * 8 + warp_in_block) * ROWS_PER_WARP;

    float wsum = 0.0f;

    if (base < N) {   // N is a multiple of 64, so the whole batch is in-bounds
        // 8 independent 16B loads issued back-to-back -> MLP ~ 8 per thread.
        const float4* x4 = reinterpret_cast<const float4*>(x);
        float4 v[ROWS_PER_WARP];
        #pragma unroll
        for (int k = 0; k < ROWS_PER_WARP; k++)
            v[k] = __ldcs(&x4[((size_t)(base + k)) * 32 + lane]);

        // Lanes 0..7 fetch the 8 labels in one coalesced transaction.
        int lab = 0;
        if (lane < ROWS_PER_WARP) lab = labels[base + lane];

        #pragma unroll
        for (int k = 0; k < ROWS_PER_WARP; k++) {
            const int label = __shfl_sync(0xffffffffu, lab, k);
            // (label & 3) is warp-uniform -> uniform select.
            const int comp = label & 3;
            float cand = (comp == 0) ? v[k].x : (comp == 1) ? v[k].y
                       : (comp == 2) ? v[k].z : v[k].w;
            const float c = __shfl_sync(0xffffffffu, cand, label >> 2);

            const float b = MARGIN - c;
            wsum += fmaxf(b + v[k].x, 0.0f);
            wsum += fmaxf(b + v[k].y, 0.0f);
            wsum += fmaxf(b + v[k].z, 0.0f);
            wsum += fmaxf(b + v[k].w, 0.0f);
        }

        // One warp reduction for all 8 rows.
        #pragma unroll
        for (int o = 16; o > 0; o >>= 1)
            wsum += __shfl_down_sync(0xffffffffu, wsum, o);

        // Each row's j == label term contributed exactly MARGIN; remove all 8.
        if (lane == 0) wsum -= MARGIN * (float)ROWS_PER_WARP;
    }

    __shared__ float  warp_sums[8];
    __shared__ bool   is_last;

    if (lane == 0) warp_sums[warp_in_block] = wsum;
    __syncthreads();

    if (threadIdx.x == 0) {
        double bsum = 0.0;
        #pragma unroll
        for (int w = 0; w < 8; w++) bsum += (double)warp_sums[w];
        atomicAdd(&g_total, bsum);
        __threadfence();
        unsigned int t = atomicAdd(&g_count, 1u);
        is_last = (t == gridDim.x - 1);
    }
    __syncthreads();

    if (is_last && threadIdx.x == 0) {
        const double total = g_total;
        // mean over N * (G-1) pairs, G = 128
        out[0] = (float)(total / ((double)N * 127.0));
        // Reset for the next (graph-replayed) call.
        g_total = 0.0;
        g_count = 0u;
    }
}

extern "C" void kernel_launch(void* const* d_in, const int* in_sizes, int n_in,
                              void* d_out, int out_size)
{
    const float* x      = (const float*)d_in[0];
    const int*   labels = (const int*)d_in[1];
    float*       out    = (float*)d_out;

    const int N = in_sizes[1];                      // labels count = rows
    const int rows_per_block = 8 * ROWS_PER_WARP;   // 64
    const int blocks = (N + rows_per_block - 1) / rows_per_block;

    margin_loss_kernel<<<blocks, 256>>>(x, labels, out, N);
}

// round 5
// speedup vs baseline: 2.5596x; 1.0654x over previous
#include <cuda_runtime.h>

#define MARGIN 0.1f
#define ROWS_PER_BATCH 4
#define NUM_BLOCKS 592          // 148 SMs * 4 CTAs -> single wave

// Persistent device scratch (no allocations allowed). Reset by the last block
// each call, so every graph replay sees the same initial state.
__device__ double       g_total = 0.0;
__device__ unsigned int g_count = 0u;

__global__ void __launch_bounds__(256, 4)
margin_loss_kernel(const float* __restrict__ x,
                   const int* __restrict__ labels,   // int32 (JAX x64 disabled)
                   float* __restrict__ out,
                   int N)
{
    const int lane     = threadIdx.x & 31;
    const int warp_gid = (blockIdx.x * blockDim.x + threadIdx.x) >> 5;
    const int nwarps   = (NUM_BLOCKS * 256) >> 5;      // 4736
    const int nbatch   = N >> 2;                       // batches of 4 rows

    const float4* x4 = reinterpret_cast<const float4*>(x);

    float wsum = 0.0f;      // per-thread hinge accumulator
    int   nrows = 0;        // rows this warp processed (for the -MARGIN fixup)

    int  b     = warp_gid;
    bool valid = (b < nbatch);

    // Prologue: load batch b.
    float4 v[ROWS_PER_BATCH];
    int    lab = 0;
    if (valid) {
        const size_t base = (size_t)b * ROWS_PER_BATCH;
        #pragma unroll
        for (int k = 0; k < ROWS_PER_BATCH; k++)
            v[k] = __ldcs(&x4[(base + k) * 32 + lane]);
        if (lane < ROWS_PER_BATCH) lab = labels[base + lane];
    }

    while (valid) {
        // Prefetch next batch (independent of current -> overlaps compute).
        const int  bn    = b + nwarps;
        const bool vnext = (bn < nbatch);
        float4 w[ROWS_PER_BATCH];
        int    lab2 = 0;
        if (vnext) {
            const size_t basen = (size_t)bn * ROWS_PER_BATCH;
            #pragma unroll
            for (int k = 0; k < ROWS_PER_BATCH; k++)
                w[k] = __ldcs(&x4[(basen + k) * 32 + lane]);
            if (lane < ROWS_PER_BATCH) lab2 = labels[basen + lane];
        }

        // Compute on the current batch.
        #pragma unroll
        for (int k = 0; k < ROWS_PER_BATCH; k++) {
            const int label = __shfl_sync(0xffffffffu, lab, k);
            const int comp  = label & 3;                 // warp-uniform
            float cand = (comp == 0) ? v[k].x : (comp == 1) ? v[k].y
                       : (comp == 2) ? v[k].z : v[k].w;
            const float c = __shfl_sync(0xffffffffu, cand, label >> 2);

            const float m = MARGIN - c;
            wsum += fmaxf(m + v[k].x, 0.0f);
            wsum += fmaxf(m + v[k].y, 0.0f);
            wsum += fmaxf(m + v[k].z, 0.0f);
            wsum += fmaxf(m + v[k].w, 0.0f);
        }
        nrows += ROWS_PER_BATCH;

        // Rotate buffers.
        #pragma unroll
        for (int k = 0; k < ROWS_PER_BATCH; k++) v[k] = w[k];
        lab   = lab2;
        b     = bn;
        valid = vnext;
    }

    // One warp reduction for everything this warp processed.
    #pragma unroll
    for (int o = 16; o > 0; o >>= 1)
        wsum += __shfl_down_sync(0xffffffffu, wsum, o);
    // Each processed row's j==label term contributed exactly MARGIN; remove.
    if (lane == 0) wsum -= MARGIN * (float)nrows;

    __shared__ float warp_sums[8];
    __shared__ bool  is_last;

    if (lane == 0) warp_sums[threadIdx.x >> 5] = wsum;
    __syncthreads();

    if (threadIdx.x == 0) {
        double bsum = 0.0;
        #pragma unroll
        for (int wi = 0; wi < 8; wi++) bsum += (double)warp_sums[wi];
        atomicAdd(&g_total, bsum);
        __threadfence();
        unsigned int t = atomicAdd(&g_count, 1u);
        is_last = (t == gridDim.x - 1);
    }
    __syncthreads();

    if (is_last && threadIdx.x == 0) {
        const double total = g_total;
        // mean over N * (G-1) pairs, G = 128
        out[0] = (float)(total / ((double)N * 127.0));
        // Reset for the next (graph-replayed) call.
        g_total = 0.0;
        g_count = 0u;
    }
}

extern "C" void kernel_launch(void* const* d_in, const int* in_sizes, int n_in,
                              void* d_out, int out_size)
{
    const float* x      = (const float*)d_in[0];
    const int*   labels = (const int*)d_in[1];
    float*       out    = (float*)d_out;

    const int N = in_sizes[1];                  // labels count = rows

    margin_loss_kernel<<<NUM_BLOCKS, 256>>>(x, labels, out, N);
}

// round 6
// speedup vs baseline: 2.7982x; 1.0932x over previous
#include <cuda_runtime.h>

#define MARGIN 0.1f
#define RPB 4                   // rows per batch
#define NUM_BLOCKS 592          // 148 SMs * 4 CTAs -> single wave

// Persistent device scratch (no allocations allowed). Reset by the last block
// each call, so every graph replay sees the same initial state.
__device__ double       g_total = 0.0;
__device__ unsigned int g_count = 0u;

__global__ void __launch_bounds__(256, 4)
margin_loss_kernel(const float* __restrict__ x,
                   const int* __restrict__ labels,   // int32 (JAX x64 disabled)
                   float* __restrict__ out,
                   int N)
{
    const int lane     = threadIdx.x & 31;
    const int warp_gid = (blockIdx.x * blockDim.x + threadIdx.x) >> 5;
    const int nwarps   = (NUM_BLOCKS * 256) >> 5;      // 4736
    const int nbatch   = N / RPB;

    const float4* x4 = reinterpret_cast<const float4*>(x);

    float wsum  = 0.0f;     // per-thread hinge accumulator
    int   nrows = 0;        // rows this warp processed (for the -MARGIN fixup)

    float4 vA[RPB], vB[RPB];
    float  cA[RPB], cB[RPB];

    // Prefetch batch bb into (vv, cc). All lanes load the same c address ->
    // one 32B sector, HW broadcast, no shuffles. c issued with default policy
    // (lands in L2) BEFORE the streaming row loads so the sector is reused.
    auto prefetch = [&](int bb, float4* vv, float* cc) {
        const size_t base = (size_t)bb * RPB;
        #pragma unroll
        for (int k = 0; k < RPB; k++) {
            const int lb = __ldg(&labels[base + k]);           // uniform, L2-hot
            cc[k] = __ldg(&x[(base + k) * 128 + lb]);          // uniform bcast
            vv[k] = __ldcs(&x4[(base + k) * 32 + lane]);       // streaming
        }
    };

    auto compute = [&](const float4* vv, const float* cc) {
        #pragma unroll
        for (int k = 0; k < RPB; k++) {
            const float m = MARGIN - cc[k];
            wsum += fmaxf(m + vv[k].x, 0.0f);
            wsum += fmaxf(m + vv[k].y, 0.0f);
            wsum += fmaxf(m + vv[k].z, 0.0f);
            wsum += fmaxf(m + vv[k].w, 0.0f);
        }
        nrows += RPB;
    };

    int b = warp_gid;
    if (b < nbatch) {
        prefetch(b, vA, cA);
        // Ping-pong pipeline: no buffer-rotation moves.
        for (;;) {
            const int b1 = b + nwarps;
            if (b1 < nbatch) prefetch(b1, vB, cB);
            compute(vA, cA);
            if (b1 >= nbatch) break;

            const int b2 = b1 + nwarps;
            if (b2 < nbatch) prefetch(b2, vA, cA);
            compute(vB, cB);
            if (b2 >= nbatch) break;
            b = b2;
        }
    }

    // One warp reduction for everything this warp processed.
    #pragma unroll
    for (int o = 16; o > 0; o >>= 1)
        wsum += __shfl_down_sync(0xffffffffu, wsum, o);
    // Each processed row's j==label term contributed exactly MARGIN; remove.
    if (lane == 0) wsum -= MARGIN * (float)nrows;

    __shared__ float warp_sums[8];
    __shared__ bool  is_last;

    if (lane == 0) warp_sums[threadIdx.x >> 5] = wsum;
    __syncthreads();

    if (threadIdx.x == 0) {
        double bsum = 0.0;
        #pragma unroll
        for (int wi = 0; wi < 8; wi++) bsum += (double)warp_sums[wi];
        atomicAdd(&g_total, bsum);
        __threadfence();
        unsigned int t = atomicAdd(&g_count, 1u);
        is_last = (t == gridDim.x - 1);
    }
    __syncthreads();

    if (is_last && threadIdx.x == 0) {
        const double total = g_total;
        // mean over N * (G-1) pairs, G = 128
        out[0] = (float)(total / ((double)N * 127.0));
        // Reset for the next (graph-replayed) call.
        g_total = 0.0;
        g_count = 0u;
    }
}

extern "C" void kernel_launch(void* const* d_in, const int* in_sizes, int n_in,
                              void* d_out, int out_size)
{
    const float* x      = (const float*)d_in[0];
    const int*   labels = (const int*)d_in[1];
    float*       out    = (float*)d_out;

    const int N = in_sizes[1];                  // labels count = rows

    margin_loss_kernel<<<NUM_BLOCKS, 256>>>(x, labels, out, N);
}